// round 2
// baseline (speedup 1.0000x reference)
#include <cuda_runtime.h>
#include <math.h>

// Problem constants
#define B 32
#define N 1024
#define D 2048   // IMG_DIM
#define E 1024   // EMBED

// ---------------- scratch (device globals; zero-alloc rule) ----------------
__device__ float g_v[B * D];        // v[b,d] = sum_e ws1_w[e,d] * cap[b,e]
__device__ float g_scores[B * N];   // raw attention logits (valid prefix only)
__device__ float g_w[B * N];        // softmax weights (0 beyond length)
__device__ float g_x[B * D];        // x[b,d] = sum_n w[b,n] * images[b,n,d]
__device__ float g_outfeat[B * E];  // x @ ws1_w^T + ws1_b
__device__ float g_feats[B * E];    // outfeat @ fc_w^T + fc_b (pre-norm)

// ---------------- K0: zero the atomic accumulators (every launch!) ----------
__global__ void k0_zero() {
    int i = blockIdx.x * blockDim.x + threadIdx.x;   // 131072 total
    if (i < B * D) g_v[i] = 0.0f;
    else           g_x[i - B * D] = 0.0f;
}

// ---------------- K1: v[b,d] = sum_e cap[b,e] * W1[e,d] ---------------------
// grid (16 d-tiles of 128, 4 b-groups of 8, 8 e-splits of 128), 128 threads
__global__ void k1_v(const float* __restrict__ cap, const float* __restrict__ W1) {
    __shared__ float sc[8][128];
    int d  = blockIdx.x * 128 + threadIdx.x;
    int bg = blockIdx.y;
    int e0 = blockIdx.z * 128;
#pragma unroll
    for (int r = 0; r < 8; r++)
        sc[r][threadIdx.x] = cap[(bg * 8 + r) * E + e0 + threadIdx.x];
    __syncthreads();
    float acc[8] = {0.f, 0.f, 0.f, 0.f, 0.f, 0.f, 0.f, 0.f};
    for (int e = 0; e < 128; e++) {
        float wv = W1[(size_t)(e0 + e) * D + d];
#pragma unroll
        for (int r = 0; r < 8; r++) acc[r] += wv * sc[r][e];
    }
#pragma unroll
    for (int r = 0; r < 8; r++)
        atomicAdd(&g_v[(bg * 8 + r) * D + d], acc[r]);
}

// ---------------- K2: scores[b,n] = images[b,n,:] . v[b,:] ------------------
// grid (128 n-tiles of 8, 32 b), 256 threads (8 warps, 1 row each). Pass 1 over images.
__global__ void k2_scores(const float* __restrict__ img, const int* __restrict__ len) {
    __shared__ float sv[D];
    int b = blockIdx.y;
    for (int i = threadIdx.x; i < D; i += 256) sv[i] = g_v[b * D + i];
    __syncthreads();
    int warp = threadIdx.x >> 5, lane = threadIdx.x & 31;
    int n = blockIdx.x * 8 + warp;
    if (n >= len[b]) return;                 // invalid rows: never read, never used
    const float4* row = (const float4*)(img + ((size_t)b * N + n) * D);
    const float4* v4  = (const float4*)sv;
    float acc = 0.f;
#pragma unroll
    for (int j = 0; j < D / 128; j++) {      // 16 iters, float4 per lane
        float4 a = row[lane + 32 * j];
        float4 v = v4[lane + 32 * j];
        acc += a.x * v.x + a.y * v.y + a.z * v.z + a.w * v.w;
    }
#pragma unroll
    for (int o = 16; o; o >>= 1) acc += __shfl_xor_sync(0xffffffffu, acc, o);
    if (lane == 0) g_scores[b * N + n] = acc;
}

// ---------------- K3: masked softmax over n, write attn output --------------
// grid 32, block 1024 (one thread per n)
__global__ void k3_softmax(const int* __restrict__ len, float* __restrict__ attn_out) {
    int b = blockIdx.x, t = threadIdx.x;
    int wid = t >> 5, lane = t & 31;
    int L = len[b];
    float s = (t < L) ? g_scores[b * N + t] : -INFINITY;
    __shared__ float red[32];
    // block max
    float m = s;
#pragma unroll
    for (int o = 16; o; o >>= 1) m = fmaxf(m, __shfl_xor_sync(0xffffffffu, m, o));
    if (lane == 0) red[wid] = m;
    __syncthreads();
    if (wid == 0) {
        float v = red[lane];
#pragma unroll
        for (int o = 16; o; o >>= 1) v = fmaxf(v, __shfl_xor_sync(0xffffffffu, v, o));
        if (lane == 0) red[0] = v;
    }
    __syncthreads();
    float M = red[0];
    __syncthreads();
    float e = (t < L) ? expf(s - M) : 0.f;
    // block sum
    float ssum = e;
#pragma unroll
    for (int o = 16; o; o >>= 1) ssum += __shfl_xor_sync(0xffffffffu, ssum, o);
    if (lane == 0) red[wid] = ssum;
    __syncthreads();
    if (wid == 0) {
        float v = red[lane];
#pragma unroll
        for (int o = 16; o; o >>= 1) v += __shfl_xor_sync(0xffffffffu, v, o);
        if (lane == 0) red[0] = v;
    }
    __syncthreads();
    float w = e / red[0];                         // 0 for invalid lanes
    g_w[b * N + t] = w;
    attn_out[b * N + t] = w;
}

// ---------------- K4: x[b,d] = sum_n w[b,n] * images[b,n,d] -----------------
// grid (4 d-tiles of 512, 32 b, 4 n-splits of 256), 128 threads (float4 each). Pass 2.
__global__ void k4_x(const float* __restrict__ img, const int* __restrict__ len) {
    __shared__ float sw[256];
    int b  = blockIdx.y;
    int n0 = blockIdx.z * 256;
    int L  = len[b];
    if (n0 >= L) return;
    for (int i = threadIdx.x; i < 256; i += 128) sw[i] = g_w[b * N + n0 + i];
    __syncthreads();
    int d = blockIdx.x * 512 + threadIdx.x * 4;
    const float* base = img + ((size_t)b * N + n0) * D + d;
    float4 acc = make_float4(0.f, 0.f, 0.f, 0.f);
    int nmax = min(256, L - n0);
#pragma unroll 4
    for (int t = 0; t < nmax; t++) {
        float w = sw[t];
        float4 a = *(const float4*)(base + (size_t)t * D);
        acc.x += w * a.x; acc.y += w * a.y; acc.z += w * a.z; acc.w += w * a.w;
    }
    float* xp = g_x + b * D + d;
    atomicAdd(xp + 0, acc.x);
    atomicAdd(xp + 1, acc.y);
    atomicAdd(xp + 2, acc.z);
    atomicAdd(xp + 3, acc.w);
}

// ---------------- K4b: init outfeat = ws1_b (Σw = 1), feats = fc_b ----------
__global__ void k4b_init(const float* __restrict__ ws1_b, const float* __restrict__ fc_b) {
    int b = blockIdx.y;
    int e = blockIdx.x * 256 + threadIdx.x;
    g_outfeat[b * E + e] = ws1_b[e];
    g_feats[b * E + e]   = fc_b[e];
}

// ---------------- GEMV body: out[b,e] += sum_k A[b,k] * W[e,k] --------------
// grid (128 e-tiles of 8 [warp per e], K/256 k-splits), 256 threads, KL=256
// NOTE: device-global A/out pointers must be bound in DEVICE code (wrappers below);
// passing __device__ symbols from host code passes the host shadow address (R1 bug).
#define KL 256
__device__ __forceinline__ void gemv32_body(const float* __restrict__ A,
                                            const float* __restrict__ W,
                                            float* __restrict__ out, int K) {
    __shared__ float sA[B * KL];
    int k0 = blockIdx.y * KL;
    for (int i = threadIdx.x; i < B * KL; i += 256) {
        int row = i >> 8, col = i & (KL - 1);
        sA[i] = A[row * K + k0 + col];
    }
    __syncthreads();
    int warp = threadIdx.x >> 5, lane = threadIdx.x & 31;
    int e = blockIdx.x * 8 + warp;
    const float4* w4 = (const float4*)(W + (size_t)e * K + k0);
    float acc[B];
#pragma unroll
    for (int b = 0; b < B; b++) acc[b] = 0.f;
#pragma unroll
    for (int j = 0; j < KL / 128; j++) {
        float4 wv = w4[lane + 32 * j];
#pragma unroll
        for (int b = 0; b < B; b++) {
            float4 a = *(const float4*)(sA + b * KL + (lane + 32 * j) * 4);
            acc[b] += wv.x * a.x + wv.y * a.y + wv.z * a.z + wv.w * a.w;
        }
    }
    float mine = 0.f;
#pragma unroll
    for (int b = 0; b < B; b++) {
        float v = acc[b];
#pragma unroll
        for (int o = 16; o; o >>= 1) v += __shfl_xor_sync(0xffffffffu, v, o);
        if (lane == b) mine = v;
    }
    atomicAdd(&out[lane * E + e], mine);
}

// K5: g_outfeat += g_x @ ws1_w^T   (K = D = 2048)
__global__ void k5_gemv(const float* __restrict__ W) {
    gemv32_body(g_x, W, g_outfeat, D);
}
// K6: g_feats += g_outfeat @ fc_w^T  (K = E = 1024)
__global__ void k6_gemv(const float* __restrict__ W) {
    gemv32_body(g_outfeat, W, g_feats, E);
}

// ---------------- K7: l2 normalize feats, write features output -------------
__global__ void k7_norm(float* __restrict__ out) {
    int b = blockIdx.x;
    __shared__ float red[8];
    int wid = threadIdx.x >> 5, lane = threadIdx.x & 31;
    float s = 0.f;
    for (int i = threadIdx.x; i < E; i += 256) {
        float v = g_feats[b * E + i];
        s += v * v;
    }
#pragma unroll
    for (int o = 16; o; o >>= 1) s += __shfl_xor_sync(0xffffffffu, s, o);
    if (lane == 0) red[wid] = s;
    __syncthreads();
    if (threadIdx.x == 0) {
        float t = 0.f;
#pragma unroll
        for (int i = 0; i < 8; i++) t += red[i];
        red[0] = 1.0f / sqrtf(t);
    }
    __syncthreads();
    float inv = red[0];
    for (int i = threadIdx.x; i < E; i += 256)
        out[b * E + i] = g_feats[b * E + i] * inv;
}

// ---------------- launch -----------------------------------------------------
extern "C" void kernel_launch(void* const* d_in, const int* in_sizes, int n_in,
                              void* d_out, int out_size) {
    const float* images = (const float*)d_in[0];  // [B,N,D]
    const float* cap    = (const float*)d_in[1];  // [B,E]
    const int*   len    = (const int*)  d_in[2];  // [B]
    const float* ws1_w  = (const float*)d_in[3];  // [E,D]
    const float* ws1_b  = (const float*)d_in[4];  // [E]
    const float* fc_w   = (const float*)d_in[5];  // [E,E]
    const float* fc_b   = (const float*)d_in[6];  // [E]
    float* out_features = (float*)d_out;          // [B,E] = first 32768
    float* out_attn     = (float*)d_out + B * E;  // [B,N,1] = next 32768

    k0_zero<<<(2 * B * D + 255) / 256, 256>>>();
    k1_v<<<dim3(D / 128, B / 8, E / 128), 128>>>(cap, ws1_w);
    k2_scores<<<dim3(N / 8, B), 256>>>(images, len);
    k3_softmax<<<B, 1024>>>(len, out_attn);
    k4_x<<<dim3(D / 512, B, N / 256), 128>>>(images, len);
    k4b_init<<<dim3(E / 256, B), 256>>>(ws1_b, fc_b);
    k5_gemv<<<dim3(E / 8, D / KL), 256>>>(ws1_w);
    k6_gemv<<<dim3(E / 8, E / KL), 256>>>(fc_w);
    k7_norm<<<B, 256>>>(out_features);
}

// round 3
// speedup vs baseline: 1.3493x; 1.3493x over previous
#include <cuda_runtime.h>
#include <math.h>

#define B 32
#define N 1024
#define D 2048   // IMG_DIM
#define E 1024   // EMBED
#define CHUNKS 16
#define CROWS (N / CHUNKS)   // 64 rows per chunk

// ---------------- scratch (device globals) ----------------
__device__ float g_v[B * D];                // v[b,d] = sum_e ws1_w[e,d]*cap[b,e]
__device__ float g_scores[B * N];           // raw logits (valid prefix only)
__device__ float g_part[B * CHUNKS * D];    // per-chunk weighted partial sums (4MB)
__device__ float g_pm[B * CHUNKS];          // per-chunk running max
__device__ float g_pl[B * CHUNKS];          // per-chunk exp-sum
__device__ float g_x[B * D];                // final attention-pooled features
__device__ float g_outfeat[B * E];          // x @ ws1_w^T + ws1_b
__device__ float g_feats[B * E];            // outfeat @ fc_w^T + fc_b

// ---------------- K0: zero g_v, init bias accumulators ----------------
__global__ void k0_init(const float* __restrict__ ws1_b, const float* __restrict__ fc_b) {
    int i = blockIdx.x * 256 + threadIdx.x;           // 131072 total
    if (i < B * D) g_v[i] = 0.0f;
    else if (i < B * D + B * E) { int j = i - B * D;       g_outfeat[j] = ws1_b[j & (E - 1)]; }
    else                        { int j = i - B * D - B * E; g_feats[j] = fc_b[j & (E - 1)]; }
}

// ---------------- K1: v[b,d] += sum_e cap[b,e]*W1[e,d] ----------------
// grid (4 d-tiles of 512, 16 e-splits of 64, 4 b-groups of 8), 128 threads, float4 d
#define K1_EC 64
__global__ __launch_bounds__(128) void k1_v(const float* __restrict__ cap,
                                            const float* __restrict__ W1) {
    __shared__ float sc[8][K1_EC];
    int tid = threadIdx.x;
    int d  = blockIdx.x * 512 + tid * 4;
    int e0 = blockIdx.y * K1_EC;
    int b0 = blockIdx.z * 8;
    for (int i = tid; i < 8 * K1_EC; i += 128)
        sc[i >> 6][i & 63] = cap[(b0 + (i >> 6)) * E + e0 + (i & 63)];
    __syncthreads();
    float4 acc[8];
#pragma unroll
    for (int r = 0; r < 8; r++) acc[r] = make_float4(0.f, 0.f, 0.f, 0.f);
#pragma unroll 4
    for (int e = 0; e < K1_EC; e++) {
        float4 wv = *(const float4*)(W1 + (size_t)(e0 + e) * D + d);
#pragma unroll
        for (int r = 0; r < 8; r++) {
            float c = sc[r][e];
            acc[r].x += c * wv.x; acc[r].y += c * wv.y;
            acc[r].z += c * wv.z; acc[r].w += c * wv.w;
        }
    }
#pragma unroll
    for (int r = 0; r < 8; r++) {
        float* p = &g_v[(size_t)(b0 + r) * D + d];
        atomicAdd(p + 0, acc[r].x); atomicAdd(p + 1, acc[r].y);
        atomicAdd(p + 2, acc[r].z); atomicAdd(p + 3, acc[r].w);
    }
}

// ---------------- K2: fused scores + online-softmax weighted partial sums ----
// SINGLE pass over images. Block = (chunk, b), 256 threads = 8 warps = 4 pairs.
// Pair p handles rows n0+p, n0+p+4, ... Each warp of a pair owns one D/2 half:
// dot via named-barrier exchange; row stays in registers for the accumulate.
__device__ __forceinline__ void pair_bar(int pair) {
    asm volatile("bar.sync %0, 64;" :: "r"(pair + 1) : "memory");
}

__global__ __launch_bounds__(256) void k2_fused(const float* __restrict__ img,
                                                const int* __restrict__ len) {
    __shared__ float sv[D];             // 8KB: v[b]
    __shared__ float accs[4][D];        // 32KB: per-pair acc staging (combine phase)
    __shared__ float sdot[4][2][2];     // [pair][buf][half]
    __shared__ float pm[4], pl[4];

    int chunk = blockIdx.x, b = blockIdx.y;
    int L  = __ldg(&len[b]);
    int n0 = chunk * CROWS;
    int tid = threadIdx.x;
    int warp = tid >> 5, lane = tid & 31;
    int pair = warp >> 1, half = warp & 1;

    for (int i = tid; i < D; i += 256) sv[i] = g_v[b * D + i];
    __syncthreads();

    const float* vbase = sv + half * (D / 2);
    float4 acc[8];
#pragma unroll
    for (int j = 0; j < 8; j++) acc[j] = make_float4(0.f, 0.f, 0.f, 0.f);
    float m = -INFINITY, l = 0.f;

    for (int t = 0; t < CROWS / 4; t++) {       // 16 rows per pair max
        int n = n0 + pair + 4 * t;
        if (n >= L) break;                      // uniform within pair
        const float* row = img + ((size_t)b * N + n) * D + half * (D / 2);
        float4 r[8];
        float dot = 0.f;
#pragma unroll
        for (int j = 0; j < 8; j++) {
            int off = (j * 32 + lane) * 4;
            r[j] = *(const float4*)(row + off);
            float4 v = *(const float4*)(vbase + off);
            dot += r[j].x * v.x + r[j].y * v.y + r[j].z * v.z + r[j].w * v.w;
        }
#pragma unroll
        for (int o = 16; o; o >>= 1) dot += __shfl_xor_sync(0xffffffffu, dot, o);
        if (lane == 0) sdot[pair][t & 1][half] = dot;
        pair_bar(pair);
        float s = sdot[pair][t & 1][0] + sdot[pair][t & 1][1];
        if (lane == 0 && half == 0) g_scores[b * N + n] = s;
        // online softmax update
        if (s > m) {
            float sc = __expf(m - s);           // m=-inf -> 0 (first row OK)
            l *= sc;
#pragma unroll
            for (int j = 0; j < 8; j++) {
                acc[j].x *= sc; acc[j].y *= sc; acc[j].z *= sc; acc[j].w *= sc;
            }
            m = s;
        }
        float e = __expf(s - m);
        l += e;
#pragma unroll
        for (int j = 0; j < 8; j++) {
            acc[j].x += e * r[j].x; acc[j].y += e * r[j].y;
            acc[j].z += e * r[j].z; acc[j].w += e * r[j].w;
        }
    }

    // stage pair accumulators to smem
#pragma unroll
    for (int j = 0; j < 8; j++)
        *(float4*)&accs[pair][half * (D / 2) + (j * 32 + lane) * 4] = acc[j];
    if (lane == 0 && half == 0) { pm[pair] = m; pl[pair] = l; }
    __syncthreads();

    // combine 4 pairs -> one chunk partial
    float mblk = fmaxf(fmaxf(pm[0], pm[1]), fmaxf(pm[2], pm[3]));
    float fac[4]; float lblk = 0.f;
#pragma unroll
    for (int p = 0; p < 4; p++) {
        fac[p] = (pl[p] > 0.f) ? __expf(pm[p] - mblk) : 0.f;
        lblk += fac[p] * pl[p];
    }
    float* part = g_part + ((size_t)(b * CHUNKS + chunk)) * D;
    for (int i = tid; i < D / 4; i += 256) {    // 2 iterations
        float4 s0 = *(const float4*)&accs[0][i * 4];
        float4 s1 = *(const float4*)&accs[1][i * 4];
        float4 s2 = *(const float4*)&accs[2][i * 4];
        float4 s3 = *(const float4*)&accs[3][i * 4];
        float4 o;
        o.x = fac[0] * s0.x + fac[1] * s1.x + fac[2] * s2.x + fac[3] * s3.x;
        o.y = fac[0] * s0.y + fac[1] * s1.y + fac[2] * s2.y + fac[3] * s3.y;
        o.z = fac[0] * s0.z + fac[1] * s1.z + fac[2] * s2.z + fac[3] * s3.z;
        o.w = fac[0] * s0.w + fac[1] * s1.w + fac[2] * s2.w + fac[3] * s3.w;
        *(float4*)(part + i * 4) = o;
    }
    if (tid == 0) { g_pm[b * CHUNKS + chunk] = mblk; g_pl[b * CHUNKS + chunk] = lblk; }
}

// ---------------- K3: merge chunk partials -> g_x; emit attention weights ---
__global__ __launch_bounds__(256) void k3_merge(const int* __restrict__ len,
                                                float* __restrict__ attn_out) {
    __shared__ float sm_[CHUNKS], sl_[CHUNKS];
    int b = blockIdx.x, tid = threadIdx.x;
    if (tid < CHUNKS) { sm_[tid] = g_pm[b * CHUNKS + tid]; sl_[tid] = g_pl[b * CHUNKS + tid]; }
    __syncthreads();
    float M = -INFINITY;
#pragma unroll
    for (int c = 0; c < CHUNKS; c++) M = fmaxf(M, sm_[c]);
    float fac[CHUNKS]; float Lsum = 0.f;
#pragma unroll
    for (int c = 0; c < CHUNKS; c++) {
        fac[c] = (sl_[c] > 0.f) ? __expf(sm_[c] - M) : 0.f;
        Lsum += fac[c] * sl_[c];
    }
    float invL = 1.0f / Lsum;
    for (int i = tid; i < D / 4; i += 256) {    // 2 iterations
        float4 acc = make_float4(0.f, 0.f, 0.f, 0.f);
#pragma unroll
        for (int c = 0; c < CHUNKS; c++) {
            float f = fac[c];
            if (f != 0.f) {
                float4 p = *(const float4*)&g_part[((size_t)(b * CHUNKS + c)) * D + i * 4];
                acc.x += f * p.x; acc.y += f * p.y; acc.z += f * p.z; acc.w += f * p.w;
            }
        }
        acc.x *= invL; acc.y *= invL; acc.z *= invL; acc.w *= invL;
        *(float4*)&g_x[b * D + i * 4] = acc;
    }
    int Lb = __ldg(&len[b]);
    for (int n = tid; n < N; n += 256)
        attn_out[b * N + n] = (n < Lb) ? __expf(g_scores[b * N + n] - M) * invL : 0.f;
}

// ---------------- GEMV body: out[b,e] += sum_k A[b,k]*W[e,k] -----------------
// device-global pointers must be bound in device code (host shadow-symbol trap)
#define KL 256
__device__ __forceinline__ void gemv32_body(const float* __restrict__ A,
                                            const float* __restrict__ W,
                                            float* __restrict__ out, int K) {
    __shared__ float sA[B * KL];
    int k0 = blockIdx.y * KL;
    for (int i = threadIdx.x; i < B * KL; i += 256) {
        int row = i >> 8, col = i & (KL - 1);
        sA[i] = A[row * K + k0 + col];
    }
    __syncthreads();
    int warp = threadIdx.x >> 5, lane = threadIdx.x & 31;
    int e = blockIdx.x * 8 + warp;
    const float4* w4 = (const float4*)(W + (size_t)e * K + k0);
    float acc[B];
#pragma unroll
    for (int b = 0; b < B; b++) acc[b] = 0.f;
#pragma unroll
    for (int j = 0; j < KL / 128; j++) {
        float4 wv = w4[lane + 32 * j];
#pragma unroll
        for (int b = 0; b < B; b++) {
            float4 a = *(const float4*)(sA + b * KL + (lane + 32 * j) * 4);
            acc[b] += wv.x * a.x + wv.y * a.y + wv.z * a.z + wv.w * a.w;
        }
    }
    float mine = 0.f;
#pragma unroll
    for (int b = 0; b < B; b++) {
        float v = acc[b];
#pragma unroll
        for (int o = 16; o; o >>= 1) v += __shfl_xor_sync(0xffffffffu, v, o);
        if (lane == b) mine = v;
    }
    atomicAdd(&out[lane * E + e], mine);
}

__global__ __launch_bounds__(256) void k5_gemv(const float* __restrict__ W) {
    gemv32_body(g_x, W, g_outfeat, D);
}
__global__ __launch_bounds__(256) void k6_gemv(const float* __restrict__ W) {
    gemv32_body(g_outfeat, W, g_feats, E);
}

// ---------------- K7: l2 normalize, write features output --------------------
__global__ __launch_bounds__(256) void k7_norm(float* __restrict__ out) {
    int b = blockIdx.x;
    __shared__ float red[8];
    int wid = threadIdx.x >> 5, lane = threadIdx.x & 31;
    float s = 0.f;
    for (int i = threadIdx.x; i < E; i += 256) {
        float v = g_feats[b * E + i];
        s += v * v;
    }
#pragma unroll
    for (int o = 16; o; o >>= 1) s += __shfl_xor_sync(0xffffffffu, s, o);
    if (lane == 0) red[wid] = s;
    __syncthreads();
    if (threadIdx.x == 0) {
        float t = 0.f;
#pragma unroll
        for (int i = 0; i < 8; i++) t += red[i];
        red[0] = 1.0f / sqrtf(t);
    }
    __syncthreads();
    float inv = red[0];
    for (int i = threadIdx.x; i < E; i += 256)
        out[b * E + i] = g_feats[b * E + i] * inv;
}

// ---------------- launch ------------------------------------------------------
extern "C" void kernel_launch(void* const* d_in, const int* in_sizes, int n_in,
                              void* d_out, int out_size) {
    const float* images = (const float*)d_in[0];  // [B,N,D]
    const float* cap    = (const float*)d_in[1];  // [B,E]
    const int*   len    = (const int*)  d_in[2];  // [B]
    const float* ws1_w  = (const float*)d_in[3];  // [E,D]
    const float* ws1_b  = (const float*)d_in[4];  // [E]
    const float* fc_w   = (const float*)d_in[5];  // [E,E]
    const float* fc_b   = (const float*)d_in[6];  // [E]
    float* out_features = (float*)d_out;          // [B,E]
    float* out_attn     = (float*)d_out + B * E;  // [B,N,1]

    k0_init<<<(B * D + 2 * B * E + 255) / 256, 256>>>(ws1_b, fc_b);
    k1_v<<<dim3(4, 16, 4), 128>>>(cap, ws1_w);
    k2_fused<<<dim3(CHUNKS, B), 256>>>(images, len);
    k3_merge<<<B, 256>>>(len, out_attn);
    k5_gemv<<<dim3(E / 8, D / KL), 256>>>(ws1_w);
    k6_gemv<<<dim3(E / 8, E / KL), 256>>>(fc_w);
    k7_norm<<<B, 256>>>(out_features);
}